// round 15
// baseline (speedup 1.0000x reference)
#include <cuda_runtime.h>
#include <cstdint>

#define BATCH 4
#define DMODEL 256
#define HH 112
#define WWID 112
#define NPIX (HH*WWID)    // 12544
#define NW 256
#define LP 49
#define TOPK 8
#define NHEAD 8
#define DH 32
#define SS 648
#define EPSI 1e-6f

// ---------------- scratch (pixel-major [b][px][256]) ----------------
__device__ float g_QF[(size_t)BATCH*NPIX*DMODEL];   // elu(q)+1
__device__ float g_KF[(size_t)BATCH*NPIX*DMODEL];   // elu(k)+1
__device__ float g_VN[(size_t)BATCH*NPIX*DMODEL];   // v/S
__device__ float g_OUT[(size_t)BATCH*NPIX*DMODEL];  // msg, pixel-major
__device__ float g_qm[BATCH*NW*DMODEL];             // RAW window SUMS (x49 of mean)
__device__ float g_km[BATCH*NW*DMODEL];             // RAW window SUMS
__device__ float g_vm[BATCH*NW*DMODEL];             // raw window means (from windowkv)
__device__ float g_KVw[(size_t)BATCH*NW*NHEAD*DH*DH];
__device__ float g_Ksw[BATCH*NW*DMODEL];
__device__ float g_KVc[BATCH*NHEAD*DH*DH];          // coarse KV (scaled /S)
__device__ float g_Ksc[BATCH*NHEAD*DH];             // coarse kf sum
__device__ float g_KVp[BATCH*NHEAD*32*DH*DH];       // coarse partials
__device__ float g_Ksp[BATCH*NHEAD*32*DH];
__device__ int   g_idx[BATCH*NW*TOPK];

// ---------------- helpers ----------------
__device__ __forceinline__ unsigned long long pk2(float lo, float hi){
    unsigned long long r;
    asm("mov.b64 %0, {%1, %2};" : "=l"(r) : "f"(lo), "f"(hi));
    return r;
}
__device__ __forceinline__ float2 upk2(unsigned long long x){
    float2 r;
    asm("mov.b64 {%0, %1}, %2;" : "=f"(r.x), "=f"(r.y) : "l"(x));
    return r;
}
__device__ __forceinline__ void fma2(unsigned long long &d, unsigned long long a, unsigned long long b){
    asm("fma.rn.f32x2 %0, %1, %2, %0;" : "+l"(d) : "l"(a), "l"(b));
}
__device__ __forceinline__ void add2(unsigned long long &d, unsigned long long a){
    asm("add.rn.f32x2 %0, %0, %1;" : "+l"(d) : "l"(a));
}
__device__ __forceinline__ float elu1(float x){
    return (x > 0.f) ? x + 1.f : __expf(x);
}

// ---------------- transpose core (raw smem, transform on store) -------------
// mode: 1 = v/S (no sums), 2 = elu + window raw-sum atomics (via block LUT)
__device__ __forceinline__ void transpose_tile(
    const float* __restrict__ src, float* __restrict__ dst,
    float* __restrict__ dsum, int b, int px0, int mode,
    float* s /*256*33*/, int* wlut /*32*/)
{
    const int tid = threadIdx.x;
    const float invS = 1.f/(float)SS;

    // load raw, float4 over px
    #pragma unroll
    for (int i = 0; i < 8; i++){
        int e = tid + i*256;
        int ch = e >> 3, px4 = (e & 7) * 4;
        float4 x = *(const float4*)(src + (size_t)(b*DMODEL + ch)*NPIX + px0 + px4);
        s[ch*33 + px4 + 0] = x.x;
        s[ch*33 + px4 + 1] = x.y;
        s[ch*33 + px4 + 2] = x.z;
        s[ch*33 + px4 + 3] = x.w;
    }
    // block-uniform window-id LUT (one div/mod chain per px, done once)
    if (mode == 2 && tid < 32){
        int gpx = px0 + tid;
        int r = gpx / WWID, c = gpx - r*WWID;
        wlut[tid] = (r/7)*16 + c/7;
    }
    __syncthreads();

    // window raw sums (thread = channel), segmented via LUT (broadcast LDS)
    if (mode == 2){
        float acc = 0.f; int curw = wlut[0];
        #pragma unroll
        for (int px = 0; px < 32; px++){
            int w = wlut[px];
            float val = s[tid*33 + px];
            if (w != curw){
                atomicAdd(&dsum[(b*NW + curw)*DMODEL + tid], acc);
                curw = w; acc = 0.f;
            }
            acc += val;
        }
        atomicAdd(&dsum[(b*NW + curw)*DMODEL + tid], acc);
    }

    // store transformed, lanes over consecutive ch
    #pragma unroll
    for (int i = 0; i < 32; i++){
        int e = tid + i*256;
        int px = e >> 8, ch = e & 255;
        float x = s[ch*33 + px];
        dst[(size_t)(b*NPIX + px0 + px)*DMODEL + ch] =
            (mode == 1) ? x*invS : elu1(x);
    }
}

// kernel 1: k (with km sums), v transpose
__global__ void __launch_bounds__(256) transpose_kv_kernel(
    const float* __restrict__ k, const float* __restrict__ v)
{
    __shared__ float s[256*33];
    __shared__ int wlut[32];
    const int mode = blockIdx.z, b = blockIdx.y;
    if (mode == 0) transpose_tile(k, g_KF, g_km, b, blockIdx.x * 32, 2, s, wlut);
    else           transpose_tile(v, g_VN, nullptr, b, blockIdx.x * 32, 1, s, wlut);
}

// ---------------- windowkv body ----------------------------------------------
__device__ __forceinline__ void windowkv_body(int bw)
{
    const int b = bw >> 8, w = bw & 255;
    const int mi = w >> 4, ni = w & 15;
    const int tid = threadIdx.x;
    const int h = tid >> 5, lane = tid & 31;
    const int dk0 = (lane >> 2) * 4, dv0 = (lane & 3) * 8;

    const size_t base = (size_t)(b*NPIX + (mi*7)*WWID + ni*7) * DMODEL;
    const float* kf = g_KF + base + h*DH + dk0;
    const float* vn = g_VN + base + h*DH + dv0;

    unsigned long long acc[4][4];
    #pragma unroll
    for (int i = 0; i < 4; i++)
        #pragma unroll
        for (int j = 0; j < 4; j++) acc[i][j] = 0ull;
    unsigned long long vs[4] = {0ull, 0ull, 0ull, 0ull};
    float s0=0.f, s1=0.f, s2=0.f, s3=0.f;

    #pragma unroll
    for (int r = 0; r < 7; r++){
        #pragma unroll
        for (int cc = 0; cc < 7; cc++){
            const size_t off = (size_t)(r*WWID + cc)*DMODEL;
            float4 kf4 = *(const float4*)(kf + off);
            ulonglong2 va = *(const ulonglong2*)(vn + off);
            ulonglong2 vb = *(const ulonglong2*)(vn + off + 4);
            unsigned long long kp;
            kp = pk2(kf4.x, kf4.x);
            fma2(acc[0][0], kp, va.x); fma2(acc[0][1], kp, va.y);
            fma2(acc[0][2], kp, vb.x); fma2(acc[0][3], kp, vb.y);
            kp = pk2(kf4.y, kf4.y);
            fma2(acc[1][0], kp, va.x); fma2(acc[1][1], kp, va.y);
            fma2(acc[1][2], kp, vb.x); fma2(acc[1][3], kp, vb.y);
            kp = pk2(kf4.z, kf4.z);
            fma2(acc[2][0], kp, va.x); fma2(acc[2][1], kp, va.y);
            fma2(acc[2][2], kp, vb.x); fma2(acc[2][3], kp, vb.y);
            kp = pk2(kf4.w, kf4.w);
            fma2(acc[3][0], kp, va.x); fma2(acc[3][1], kp, va.y);
            fma2(acc[3][2], kp, vb.x); fma2(acc[3][3], kp, vb.y);
            s0 += kf4.x; s1 += kf4.y; s2 += kf4.z; s3 += kf4.w;
            add2(vs[0], va.x); add2(vs[1], va.y);
            add2(vs[2], vb.x); add2(vs[3], vb.y);
        }
    }

    float* o = g_KVw + (size_t)bw*(NHEAD*DH*DH) + h*DH*DH + dk0*DH + dv0;
    #pragma unroll
    for (int i = 0; i < 4; i++)
        #pragma unroll
        for (int j = 0; j < 4; j++){
            float2 t = upk2(acc[i][j]);
            *(float2*)(o + i*DH + 2*j) = t;
        }
    if ((lane & 3) == 0){
        float* ks = g_Ksw + bw*DMODEL + h*DH + dk0;
        ks[0]=s0; ks[1]=s1; ks[2]=s2; ks[3]=s3;
    }
    if (dk0 == 0){
        const float f = (float)SS/49.f;   // vm raw mean from VN sums
        float* vmp = g_vm + bw*DMODEL + h*DH + dv0;
        #pragma unroll
        for (int j = 0; j < 4; j++){
            float2 t = upk2(vs[j]);
            vmp[2*j]   = t.x * f;
            vmp[2*j+1] = t.y * f;
        }
    }
}

// kernel 2 (fused): windowkv (blocks 0..1023) + transpose_q (blocks 1024..2591)
__global__ void __launch_bounds__(256) fused_mid_kernel(const float* __restrict__ q)
{
    __shared__ float s[256*33];
    __shared__ int wlut[32];
    const int bx = blockIdx.x;
    if (bx < BATCH*NW){
        windowkv_body(bx);
    } else {
        int t = bx - BATCH*NW;          // 0..1567
        int b = t / (NPIX/32);
        int tile = t - b*(NPIX/32);
        transpose_tile(q, g_QF, g_qm, b, tile * 32, 2, s, wlut);
    }
}

// ---------------- coarse_part body -------------------------------------------
__device__ __forceinline__ void coarse_part_body(int bh, int split)
{
    const int b = bh >> 3, h = bh & 7;
    const int tid = threadIdx.x;
    const int dk = tid >> 3, q4 = tid & 7;
    float a0=0.f,a1=0.f,a2=0.f,a3=0.f, ks=0.f;
    const int w0 = split * 8;
    const float inv49 = 1.f/49.f;
    #pragma unroll
    for (int w = w0; w < w0 + 8; w++){
        float ksum = g_km[(b*NW + w)*DMODEL + h*DH + dk];
        float kf = elu1(ksum * inv49);      // km stored as raw sum
        float4 vr = *(const float4*)&g_vm[(b*NW + w)*DMODEL + h*DH + q4*4];
        a0 += kf*vr.x; a1 += kf*vr.y; a2 += kf*vr.z; a3 += kf*vr.w;
        ks += kf;
    }
    float* o = &g_KVp[((bh*32 + split)*DH + dk)*DH + q4*4];
    o[0]=a0; o[1]=a1; o[2]=a2; o[3]=a3;
    if (q4 == 0) g_Ksp[(bh*32 + split)*DH + dk] = ks;
}

// ---------------- simtopk body ------------------------------------------------
__device__ __forceinline__ void simtopk_body(int b, int qr0,
                                             float* qsh, float* ksh, float* ssh)
{
    const int tid = threadIdx.x;

    #pragma unroll
    for (int i = 0; i < 4; i++){
        int e = tid + i*256;
        qsh[e] = g_qm[(b*NW + qr0 + (e >> 8))*DMODEL + (e & 255)];
    }
    float acc[4] = {0.f, 0.f, 0.f, 0.f};

    for (int ct = 0; ct < 8; ct++){
        __syncthreads();
        int ch0 = ct * 32;
        #pragma unroll
        for (int i = 0; i < 32; i++){
            int e = tid + i*256;
            int row = e >> 5, ch = e & 31;
            ksh[row*33 + ch] = g_km[(b*NW + row)*DMODEL + ch0 + ch];
        }
        __syncthreads();
        #pragma unroll
        for (int ch = 0; ch < 32; ch++){
            float kv = ksh[tid*33 + ch];
            #pragma unroll
            for (int r = 0; r < 4; r++)
                acc[r] += qsh[r*256 + ch0 + ch] * kv;
        }
    }
    __syncthreads();
    #pragma unroll
    for (int r = 0; r < 4; r++) ssh[r*256 + tid] = acc[r];
    __syncthreads();

    int w = tid >> 5, lane = tid & 31;
    if (w < 4){
        float* row = &ssh[w*256];
        for (int j = 0; j < TOPK; j++){
            float lv = -3.0e38f; int li = 1 << 30;
            #pragma unroll
            for (int c0 = 0; c0 < 256; c0 += 32){
                float v2 = row[c0 + lane];
                if (v2 > lv) { lv = v2; li = c0 + lane; }
            }
            #pragma unroll
            for (int off = 16; off; off >>= 1){
                float ov = __shfl_down_sync(0xffffffffu, lv, off);
                int   oi = __shfl_down_sync(0xffffffffu, li, off);
                if (ov > lv || (ov == lv && oi < li)) { lv = ov; li = oi; }
            }
            li = __shfl_sync(0xffffffffu, li, 0);
            if (lane == 0){
                g_idx[(b*NW + qr0 + w)*TOPK + j] = li;
                row[li] = -3.0e38f;
            }
            __syncwarp();
        }
    }
}

// kernel 3 (fused): coarse_part (blocks 0..1023) + simtopk (blocks 1024..1279)
__global__ void __launch_bounds__(256) fused_sim_kernel()
{
    __shared__ float qsh[4*256];
    __shared__ float ksh[256*33];
    __shared__ float ssh[4*256];
    const int bx = blockIdx.x;
    if (bx < 1024){
        coarse_part_body(bx >> 5, bx & 31);
    } else {
        int t = bx - 1024;              // 0..255
        simtopk_body(t >> 6, (t & 63) * 4, qsh, ksh, ssh);
    }
}

// ---------------- kernel 4: coarse reduce (grid 32 x 4, full-MLP) ----------
__global__ void coarse_reduce_kernel()
{
    const int bh = blockIdx.x;
    const int t = blockIdx.y*256 + threadIdx.x;   // output 0..1023
    const float invS = 1.f/(float)SS;
    float a = 0.f;
    #pragma unroll
    for (int s = 0; s < 32; s++)
        a += g_KVp[(size_t)(bh*32 + s)*1024 + t];
    g_KVc[bh*1024 + t] = a * invS;
    if (blockIdx.y == 0 && threadIdx.x < DH){
        float ks = 0.f;
        #pragma unroll
        for (int s = 0; s < 32; s++)
            ks += g_Ksp[(bh*32 + s)*DH + threadIdx.x];
        g_Ksc[bh*DH + threadIdx.x] = ks;
    }
}

// ---------------- kernel 5: gather-sum KV + epilogue (pixel-major out) -------
__global__ void __launch_bounds__(256) attn_kernel()
{
    __shared__ float KVsh[NHEAD*DH*DH];
    __shared__ float Kssh[DMODEL];
    __shared__ float Zsh[LP*NHEAD];
    __shared__ int widx[TOPK];

    const int b  = blockIdx.x >> 8;
    const int qw = blockIdx.x & 255;
    const int mi = qw >> 4, ni = qw & 15;
    const int tid = threadIdx.x;
    const int h = tid >> 5, lane = tid & 31;

    if (tid < TOPK) widx[tid] = g_idx[(b*NW + qw)*TOPK + tid];
    __syncthreads();

    {
        float ks = g_Ksc[b*DMODEL + tid];
        #pragma unroll
        for (int j = 0; j < TOPK; j++)
            ks += g_Ksw[(b*NW + widx[j])*DMODEL + tid];
        Kssh[tid] = ks;
    }

    const float4* cb = (const float4*)g_KVc + b*2048;
    #pragma unroll
    for (int it = 0; it < 8; it++){
        int t = tid + it*256;
        float ax=0.f, ay=0.f, az=0.f, aw=0.f;
        #pragma unroll
        for (int j = 0; j < TOPK; j++){
            float4 x = *((const float4*)g_KVw + (size_t)(b*NW + widx[j])*2048 + t);
            ax += x.x; ay += x.y; az += x.z; aw += x.w;
        }
        float4 c = cb[t];
        ((float4*)KVsh)[t] = make_float4(c.x + ax, c.y + ay, c.z + az, c.w + aw);
    }
    __syncthreads();

    const size_t pxbase = (size_t)(b*NPIX + (mi*7)*WWID + ni*7);
    const float* qfbase = g_QF + pxbase*DMODEL;

    // Z per (l, head)
    for (int pr = tid; pr < LP*NHEAD; pr += 256){
        int l = pr >> 3, hh = pr & 7;
        int r = l / 7, cc = l - r*7;
        const float* qf = qfbase + (size_t)(r*WWID + cc)*DMODEL + hh*DH;
        float dot = 0.f;
        #pragma unroll
        for (int t = 0; t < 8; t++){
            float4 q4 = *(const float4*)(qf + t*4);
            const float* kr = &Kssh[hh*DH + t*4];
            dot += q4.x*kr[0] + q4.y*kr[1] + q4.z*kr[2] + q4.w*kr[3];
        }
        Zsh[l*NHEAD + hh] = 1.f/(dot + EPSI);
    }
    __syncthreads();

    // msg: thread = channel (h = tid>>5, dv = lane), KV column packed in regs
    {
        unsigned long long kvc[16];
        #pragma unroll
        for (int t = 0; t < 16; t++)
            kvc[t] = pk2(KVsh[(h*DH + 2*t)*DH + lane],
                         KVsh[(h*DH + 2*t+1)*DH + lane]);

        float* ob = g_OUT + pxbase*DMODEL + tid;
        #pragma unroll
        for (int r = 0; r < 7; r++){
            #pragma unroll
            for (int cc = 0; cc < 7; cc++){
                int l = r*7 + cc;
                const float* qf = qfbase + (size_t)(r*WWID + cc)*DMODEL + h*DH;
                unsigned long long a2 = 0ull;
                #pragma unroll
                for (int t = 0; t < 8; t++){
                    float4 q4 = *(const float4*)(qf + t*4);
                    fma2(a2, pk2(q4.x, q4.y), kvc[2*t]);
                    fma2(a2, pk2(q4.z, q4.w), kvc[2*t+1]);
                }
                float2 p2 = upk2(a2);
                ob[(size_t)(r*WWID + cc)*DMODEL] =
                    (p2.x + p2.y) * Zsh[l*NHEAD + h] * (float)SS;
            }
        }
    }
}

// ---------------- kernel 6: out-transpose ------------------------------------
__global__ void __launch_bounds__(256) transpose_out_kernel(float* __restrict__ out)
{
    const int b = blockIdx.y;
    const int px0 = blockIdx.x * 32;
    __shared__ float s[256*33];
    const int tid = threadIdx.x;

    #pragma unroll
    for (int i = 0; i < 32; i++){
        int e = tid + i*256;
        int px = e >> 8, ch = e & 255;
        s[ch*33 + px] = g_OUT[(size_t)(b*NPIX + px0 + px)*DMODEL + ch];
    }
    __syncthreads();
    #pragma unroll
    for (int i = 0; i < 32; i++){
        int e = tid + i*256;
        int ch = e >> 5, px = e & 31;
        out[(size_t)(b*DMODEL + ch)*NPIX + px0 + px] = s[ch*33 + px];
    }
}

// ---------------- launch ------------------------------------------------------
extern "C" void kernel_launch(void* const* d_in, const int* in_sizes, int n_in,
                              void* d_out, int out_size)
{
    const float* q = (const float*)d_in[0];
    const float* k = (const float*)d_in[1];
    const float* v = (const float*)d_in[2];
    float* out = (float*)d_out;

    void *qm_ptr = nullptr, *km_ptr = nullptr;
    cudaGetSymbolAddress(&qm_ptr, g_qm);
    cudaGetSymbolAddress(&km_ptr, g_km);
    cudaMemsetAsync(qm_ptr, 0, sizeof(float)*BATCH*NW*DMODEL);
    cudaMemsetAsync(km_ptr, 0, sizeof(float)*BATCH*NW*DMODEL);

    transpose_kv_kernel<<<dim3(NPIX/32, BATCH, 2), 256>>>(k, v);
    fused_mid_kernel<<<BATCH*NW + (NPIX/32)*BATCH, 256>>>(q);
    fused_sim_kernel<<<1024 + 256, 256>>>();
    coarse_reduce_kernel<<<dim3(32, 4), 256>>>();
    attn_kernel<<<BATCH*NW, 256>>>();
    transpose_out_kernel<<<dim3(NPIX/32, BATCH), 256>>>(out);
}

// round 16
// speedup vs baseline: 1.0147x; 1.0147x over previous
#include <cuda_runtime.h>
#include <cstdint>

#define BATCH 4
#define DMODEL 256
#define HH 112
#define WWID 112
#define NPIX (HH*WWID)    // 12544
#define NW 256
#define LP 49
#define TOPK 8
#define NHEAD 8
#define DH 32
#define SS 648
#define EPSI 1e-6f

// ---------------- scratch (pixel-major [b][px][256]) ----------------
__device__ float g_QF[(size_t)BATCH*NPIX*DMODEL];   // elu(q)+1
__device__ float g_KF[(size_t)BATCH*NPIX*DMODEL];   // elu(k)+1
__device__ float g_VN[(size_t)BATCH*NPIX*DMODEL];   // v/S
__device__ float g_OUT[(size_t)BATCH*NPIX*DMODEL];  // msg, pixel-major
__device__ float g_qkm[2*BATCH*NW*DMODEL];          // [qm | km] RAW window SUMS (one memset)
#define QM_OFF 0
#define KM_OFF (BATCH*NW*DMODEL)
__device__ float g_vm[BATCH*NW*DMODEL];             // raw window means (from windowkv)
__device__ float g_KVw[(size_t)BATCH*NW*NHEAD*DH*DH];
__device__ float g_Ksw[BATCH*NW*DMODEL];
__device__ float g_KVc[BATCH*NHEAD*DH*DH];          // coarse KV (scaled /S)
__device__ float g_Ksc[BATCH*NHEAD*DH];             // coarse kf sum
__device__ float g_KVp[BATCH*NHEAD*32*DH*DH];       // coarse partials
__device__ float g_Ksp[BATCH*NHEAD*32*DH];
__device__ int   g_idx[BATCH*NW*TOPK];

// ---------------- helpers ----------------
__device__ __forceinline__ unsigned long long pk2(float lo, float hi){
    unsigned long long r;
    asm("mov.b64 %0, {%1, %2};" : "=l"(r) : "f"(lo), "f"(hi));
    return r;
}
__device__ __forceinline__ float2 upk2(unsigned long long x){
    float2 r;
    asm("mov.b64 {%0, %1}, %2;" : "=f"(r.x), "=f"(r.y) : "l"(x));
    return r;
}
__device__ __forceinline__ void fma2(unsigned long long &d, unsigned long long a, unsigned long long b){
    asm("fma.rn.f32x2 %0, %1, %2, %0;" : "+l"(d) : "l"(a), "l"(b));
}
__device__ __forceinline__ void add2(unsigned long long &d, unsigned long long a){
    asm("add.rn.f32x2 %0, %0, %1;" : "+l"(d) : "l"(a));
}
__device__ __forceinline__ float elu1(float x){
    return (x > 0.f) ? x + 1.f : __expf(x);
}

// ---------------- transpose core (raw smem, transform on store) -------------
// mode: 1 = v/S (no sums), 2 = elu + window raw-sum atomics
__device__ __forceinline__ void transpose_tile(
    const float* __restrict__ src, float* __restrict__ dst,
    float* __restrict__ dsum, int b, int px0, int mode, float* s /*256*33*/)
{
    const int tid = threadIdx.x;
    const float invS = 1.f/(float)SS;

    // load raw, float4 over px
    #pragma unroll
    for (int i = 0; i < 8; i++){
        int e = tid + i*256;
        int ch = e >> 3, px4 = (e & 7) * 4;
        float4 x = *(const float4*)(src + (size_t)(b*DMODEL + ch)*NPIX + px0 + px4);
        s[ch*33 + px4 + 0] = x.x;
        s[ch*33 + px4 + 1] = x.y;
        s[ch*33 + px4 + 2] = x.z;
        s[ch*33 + px4 + 3] = x.w;
    }
    __syncthreads();

    // window raw sums (thread = channel), segmented over the 32 px
    if (mode == 2){
        float acc = 0.f; int curw = -1;
        #pragma unroll 8
        for (int px = 0; px < 32; px++){
            int gpx = px0 + px;
            int r = gpx / WWID, c = gpx - r*WWID;
            int w = (r/7)*16 + c/7;
            float val = s[tid*33 + px];
            if (w != curw){
                if (curw >= 0) atomicAdd(&dsum[(b*NW + curw)*DMODEL + tid], acc);
                curw = w; acc = 0.f;
            }
            acc += val;
        }
        atomicAdd(&dsum[(b*NW + curw)*DMODEL + tid], acc);
    }

    // store transformed, lanes over consecutive ch
    #pragma unroll
    for (int i = 0; i < 32; i++){
        int e = tid + i*256;
        int px = e >> 8, ch = e & 255;
        float x = s[ch*33 + px];
        dst[(size_t)(b*NPIX + px0 + px)*DMODEL + ch] =
            (mode == 1) ? x*invS : elu1(x);
    }
}

// kernel 1: k (with km sums), v transpose
__global__ void __launch_bounds__(256) transpose_kv_kernel(
    const float* __restrict__ k, const float* __restrict__ v)
{
    __shared__ float s[256*33];
    const int mode = blockIdx.z, b = blockIdx.y;
    if (mode == 0) transpose_tile(k, g_KF, g_qkm + KM_OFF, b, blockIdx.x * 32, 2, s);
    else           transpose_tile(v, g_VN, nullptr, b, blockIdx.x * 32, 1, s);
}

// ---------------- windowkv body ----------------------------------------------
__device__ __forceinline__ void windowkv_body(int bw)
{
    const int b = bw >> 8, w = bw & 255;
    const int mi = w >> 4, ni = w & 15;
    const int tid = threadIdx.x;
    const int h = tid >> 5, lane = tid & 31;
    const int dk0 = (lane >> 2) * 4, dv0 = (lane & 3) * 8;

    const size_t base = (size_t)(b*NPIX + (mi*7)*WWID + ni*7) * DMODEL;
    const float* kf = g_KF + base + h*DH + dk0;
    const float* vn = g_VN + base + h*DH + dv0;

    unsigned long long acc[4][4];
    #pragma unroll
    for (int i = 0; i < 4; i++)
        #pragma unroll
        for (int j = 0; j < 4; j++) acc[i][j] = 0ull;
    unsigned long long vs[4] = {0ull, 0ull, 0ull, 0ull};
    float s0=0.f, s1=0.f, s2=0.f, s3=0.f;

    #pragma unroll
    for (int r = 0; r < 7; r++){
        #pragma unroll
        for (int cc = 0; cc < 7; cc++){
            const size_t off = (size_t)(r*WWID + cc)*DMODEL;
            float4 kf4 = *(const float4*)(kf + off);
            ulonglong2 va = *(const ulonglong2*)(vn + off);
            ulonglong2 vb = *(const ulonglong2*)(vn + off + 4);
            unsigned long long kp;
            kp = pk2(kf4.x, kf4.x);
            fma2(acc[0][0], kp, va.x); fma2(acc[0][1], kp, va.y);
            fma2(acc[0][2], kp, vb.x); fma2(acc[0][3], kp, vb.y);
            kp = pk2(kf4.y, kf4.y);
            fma2(acc[1][0], kp, va.x); fma2(acc[1][1], kp, va.y);
            fma2(acc[1][2], kp, vb.x); fma2(acc[1][3], kp, vb.y);
            kp = pk2(kf4.z, kf4.z);
            fma2(acc[2][0], kp, va.x); fma2(acc[2][1], kp, va.y);
            fma2(acc[2][2], kp, vb.x); fma2(acc[2][3], kp, vb.y);
            kp = pk2(kf4.w, kf4.w);
            fma2(acc[3][0], kp, va.x); fma2(acc[3][1], kp, va.y);
            fma2(acc[3][2], kp, vb.x); fma2(acc[3][3], kp, vb.y);
            s0 += kf4.x; s1 += kf4.y; s2 += kf4.z; s3 += kf4.w;
            add2(vs[0], va.x); add2(vs[1], va.y);
            add2(vs[2], vb.x); add2(vs[3], vb.y);
        }
    }

    float* o = g_KVw + (size_t)bw*(NHEAD*DH*DH) + h*DH*DH + dk0*DH + dv0;
    #pragma unroll
    for (int i = 0; i < 4; i++)
        #pragma unroll
        for (int j = 0; j < 4; j++){
            float2 t = upk2(acc[i][j]);
            *(float2*)(o + i*DH + 2*j) = t;
        }
    if ((lane & 3) == 0){
        float* ks = g_Ksw + bw*DMODEL + h*DH + dk0;
        ks[0]=s0; ks[1]=s1; ks[2]=s2; ks[3]=s3;
    }
    if (dk0 == 0){
        const float f = (float)SS/49.f;   // vm raw mean from VN sums
        float* vmp = g_vm + bw*DMODEL + h*DH + dv0;
        #pragma unroll
        for (int j = 0; j < 4; j++){
            float2 t = upk2(vs[j]);
            vmp[2*j]   = t.x * f;
            vmp[2*j+1] = t.y * f;
        }
    }
}

// kernel 2 (fused): windowkv (blocks 0..1023) + transpose_q (blocks 1024..2591)
__global__ void __launch_bounds__(256) fused_mid_kernel(const float* __restrict__ q)
{
    __shared__ float s[256*33];
    const int bx = blockIdx.x;
    if (bx < BATCH*NW){
        windowkv_body(bx);
    } else {
        int t = bx - BATCH*NW;          // 0..1567
        int b = t / (NPIX/32);
        int tile = t - b*(NPIX/32);
        transpose_tile(q, g_QF, g_qkm + QM_OFF, b, tile * 32, 2, s);
    }
}

// ---------------- coarse_part body -------------------------------------------
__device__ __forceinline__ void coarse_part_body(int bh, int split)
{
    const int b = bh >> 3, h = bh & 7;
    const int tid = threadIdx.x;
    const int dk = tid >> 3, q4 = tid & 7;
    float a0=0.f,a1=0.f,a2=0.f,a3=0.f, ks=0.f;
    const int w0 = split * 8;
    const float inv49 = 1.f/49.f;
    #pragma unroll
    for (int w = w0; w < w0 + 8; w++){
        float ksum = g_qkm[KM_OFF + (b*NW + w)*DMODEL + h*DH + dk];
        float kf = elu1(ksum * inv49);      // km stored as raw sum
        float4 vr = *(const float4*)&g_vm[(b*NW + w)*DMODEL + h*DH + q4*4];
        a0 += kf*vr.x; a1 += kf*vr.y; a2 += kf*vr.z; a3 += kf*vr.w;
        ks += kf;
    }
    float* o = &g_KVp[((bh*32 + split)*DH + dk)*DH + q4*4];
    o[0]=a0; o[1]=a1; o[2]=a2; o[3]=a3;
    if (q4 == 0) g_Ksp[(bh*32 + split)*DH + dk] = ks;
}

// ---------------- simtopk body ------------------------------------------------
__device__ __forceinline__ void simtopk_body(int b, int qr0,
                                             float* qsh, float* ksh, float* ssh)
{
    const int tid = threadIdx.x;

    #pragma unroll
    for (int i = 0; i < 4; i++){
        int e = tid + i*256;
        qsh[e] = g_qkm[QM_OFF + (b*NW + qr0 + (e >> 8))*DMODEL + (e & 255)];
    }
    float acc[4] = {0.f, 0.f, 0.f, 0.f};

    for (int ct = 0; ct < 8; ct++){
        __syncthreads();
        int ch0 = ct * 32;
        #pragma unroll
        for (int i = 0; i < 32; i++){
            int e = tid + i*256;
            int row = e >> 5, ch = e & 31;
            ksh[row*33 + ch] = g_qkm[KM_OFF + (b*NW + row)*DMODEL + ch0 + ch];
        }
        __syncthreads();
        #pragma unroll
        for (int ch = 0; ch < 32; ch++){
            float kv = ksh[tid*33 + ch];
            #pragma unroll
            for (int r = 0; r < 4; r++)
                acc[r] += qsh[r*256 + ch0 + ch] * kv;
        }
    }
    __syncthreads();
    #pragma unroll
    for (int r = 0; r < 4; r++) ssh[r*256 + tid] = acc[r];
    __syncthreads();

    int w = tid >> 5, lane = tid & 31;
    if (w < 4){
        float* row = &ssh[w*256];
        for (int j = 0; j < TOPK; j++){
            float lv = -3.0e38f; int li = 1 << 30;
            #pragma unroll
            for (int c0 = 0; c0 < 256; c0 += 32){
                float v2 = row[c0 + lane];
                if (v2 > lv) { lv = v2; li = c0 + lane; }
            }
            #pragma unroll
            for (int off = 16; off; off >>= 1){
                float ov = __shfl_down_sync(0xffffffffu, lv, off);
                int   oi = __shfl_down_sync(0xffffffffu, li, off);
                if (ov > lv || (ov == lv && oi < li)) { lv = ov; li = oi; }
            }
            li = __shfl_sync(0xffffffffu, li, 0);
            if (lane == 0){
                g_idx[(b*NW + qr0 + w)*TOPK + j] = li;
                row[li] = -3.0e38f;
            }
            __syncwarp();
        }
    }
}

// kernel 3 (fused): coarse_part (blocks 0..1023) + simtopk (blocks 1024..1279)
__global__ void __launch_bounds__(256) fused_sim_kernel()
{
    __shared__ float qsh[4*256];
    __shared__ float ksh[256*33];
    __shared__ float ssh[4*256];
    const int bx = blockIdx.x;
    if (bx < 1024){
        coarse_part_body(bx >> 5, bx & 31);
    } else {
        int t = bx - 1024;              // 0..255
        simtopk_body(t >> 6, (t & 63) * 4, qsh, ksh, ssh);
    }
}

// ---------------- kernel 4: coarse reduce (grid 32 x 4, full-MLP) ----------
__global__ void coarse_reduce_kernel()
{
    const int bh = blockIdx.x;
    const int t = blockIdx.y*256 + threadIdx.x;   // output 0..1023
    const float invS = 1.f/(float)SS;
    float a = 0.f;
    #pragma unroll
    for (int s = 0; s < 32; s++)
        a += g_KVp[(size_t)(bh*32 + s)*1024 + t];
    g_KVc[bh*1024 + t] = a * invS;
    if (blockIdx.y == 0 && threadIdx.x < DH){
        float ks = 0.f;
        #pragma unroll
        for (int s = 0; s < 32; s++)
            ks += g_Ksp[(bh*32 + s)*DH + threadIdx.x];
        g_Ksc[bh*DH + threadIdx.x] = ks;
    }
}

// ---------------- kernel 5: gather-sum KV + epilogue (pixel-major out) -------
__global__ void __launch_bounds__(256) attn_kernel()
{
    __shared__ float KVsh[NHEAD*DH*DH];
    __shared__ float Kssh[DMODEL];
    __shared__ float Zsh[LP*NHEAD];
    __shared__ int widx[TOPK];

    const int b  = blockIdx.x >> 8;
    const int qw = blockIdx.x & 255;
    const int mi = qw >> 4, ni = qw & 15;
    const int tid = threadIdx.x;
    const int h = tid >> 5, lane = tid & 31;

    if (tid < TOPK) widx[tid] = g_idx[(b*NW + qw)*TOPK + tid];
    __syncthreads();

    {
        float ks = g_Ksc[b*DMODEL + tid];
        #pragma unroll
        for (int j = 0; j < TOPK; j++)
            ks += g_Ksw[(b*NW + widx[j])*DMODEL + tid];
        Kssh[tid] = ks;
    }

    const float4* cb = (const float4*)g_KVc + b*2048;
    #pragma unroll
    for (int it = 0; it < 8; it++){
        int t = tid + it*256;
        float ax=0.f, ay=0.f, az=0.f, aw=0.f;
        #pragma unroll
        for (int j = 0; j < TOPK; j++){
            float4 x = *((const float4*)g_KVw + (size_t)(b*NW + widx[j])*2048 + t);
            ax += x.x; ay += x.y; az += x.z; aw += x.w;
        }
        float4 c = cb[t];
        ((float4*)KVsh)[t] = make_float4(c.x + ax, c.y + ay, c.z + az, c.w + aw);
    }
    __syncthreads();

    const size_t pxbase = (size_t)(b*NPIX + (mi*7)*WWID + ni*7);
    const float* qfbase = g_QF + pxbase*DMODEL;

    // Z per (l, head)
    for (int pr = tid; pr < LP*NHEAD; pr += 256){
        int l = pr >> 3, hh = pr & 7;
        int r = l / 7, cc = l - r*7;
        const float* qf = qfbase + (size_t)(r*WWID + cc)*DMODEL + hh*DH;
        float dot = 0.f;
        #pragma unroll
        for (int t = 0; t < 8; t++){
            float4 q4 = *(const float4*)(qf + t*4);
            const float* kr = &Kssh[hh*DH + t*4];
            dot += q4.x*kr[0] + q4.y*kr[1] + q4.z*kr[2] + q4.w*kr[3];
        }
        Zsh[l*NHEAD + hh] = 1.f/(dot + EPSI);
    }
    __syncthreads();

    // msg: thread = channel (h = tid>>5, dv = lane), KV column packed in regs
    {
        unsigned long long kvc[16];
        #pragma unroll
        for (int t = 0; t < 16; t++)
            kvc[t] = pk2(KVsh[(h*DH + 2*t)*DH + lane],
                         KVsh[(h*DH + 2*t+1)*DH + lane]);

        float* ob = g_OUT + pxbase*DMODEL + tid;
        #pragma unroll
        for (int r = 0; r < 7; r++){
            #pragma unroll
            for (int cc = 0; cc < 7; cc++){
                int l = r*7 + cc;
                const float* qf = qfbase + (size_t)(r*WWID + cc)*DMODEL + h*DH;
                unsigned long long a2 = 0ull;
                #pragma unroll
                for (int t = 0; t < 8; t++){
                    float4 q4 = *(const float4*)(qf + t*4);
                    fma2(a2, pk2(q4.x, q4.y), kvc[2*t]);
                    fma2(a2, pk2(q4.z, q4.w), kvc[2*t+1]);
                }
                float2 p2 = upk2(a2);
                ob[(size_t)(r*WWID + cc)*DMODEL] =
                    (p2.x + p2.y) * Zsh[l*NHEAD + h] * (float)SS;
            }
        }
    }
}

// ---------------- kernel 6: out-transpose ------------------------------------
__global__ void __launch_bounds__(256) transpose_out_kernel(float* __restrict__ out)
{
    const int b = blockIdx.y;
    const int px0 = blockIdx.x * 32;
    __shared__ float s[256*33];
    const int tid = threadIdx.x;

    #pragma unroll
    for (int i = 0; i < 32; i++){
        int e = tid + i*256;
        int px = e >> 8, ch = e & 255;
        s[ch*33 + px] = g_OUT[(size_t)(b*NPIX + px0 + px)*DMODEL + ch];
    }
    __syncthreads();
    #pragma unroll
    for (int i = 0; i < 32; i++){
        int e = tid + i*256;
        int ch = e >> 5, px = e & 31;
        out[(size_t)(b*DMODEL + ch)*NPIX + px0 + px] = s[ch*33 + px];
    }
}

// ---------------- launch ------------------------------------------------------
extern "C" void kernel_launch(void* const* d_in, const int* in_sizes, int n_in,
                              void* d_out, int out_size)
{
    const float* q = (const float*)d_in[0];
    const float* k = (const float*)d_in[1];
    const float* v = (const float*)d_in[2];
    float* out = (float*)d_out;

    void *qkm_ptr = nullptr;
    cudaGetSymbolAddress(&qkm_ptr, g_qkm);
    cudaMemsetAsync(qkm_ptr, 0, sizeof(float)*2*BATCH*NW*DMODEL);

    transpose_kv_kernel<<<dim3(NPIX/32, BATCH, 2), 256>>>(k, v);
    fused_mid_kernel<<<BATCH*NW + (NPIX/32)*BATCH, 256>>>(q);
    fused_sim_kernel<<<1024 + 256, 256>>>();
    coarse_reduce_kernel<<<dim3(32, 4), 256>>>();
    attn_kernel<<<BATCH*NW, 256>>>();
    transpose_out_kernel<<<dim3(NPIX/32, BATCH), 256>>>(out);
}